// round 12
// baseline (speedup 1.0000x reference)
#include <cuda_runtime.h>
#include <stdint.h>

// EGCN pull-mode, consolidated pipeline (5 launches):
//   K1 norm+hist (block-role split)
//   K2 single-pass decoupled-lookback scan -> g_off, g_cur
//   K3 scatter edges into dst-sorted records
//   K4 pull layer 1: x1 = A x0
//   K5 pull layer 2 (fused): out = x0 + x1 + A x1, plus state re-zeroing
// N=100000, DIM=64, E=1.6M. adj arrives int32.

constexpr int N_NODES = 100000;
constexpr int DIM     = 64;
constexpr int DIM4    = DIM / 4;     // 16 float4 per row
constexpr int MAX_E   = 1600000;
constexpr int SCAN_B  = 512;
constexpr int NUM_SB  = (N_NODES + SCAN_B - 1) / SCAN_B;      // 196

// ---- device scratch (allocation-free; zero-initialized at module load) ----
__device__ float4 g_x0[(long long)N_NODES * DIM4];
__device__ float4 g_x1[(long long)N_NODES * DIM4];
__device__ int    g_cnt[N_NODES];                 // in-degree histogram (must be 0 at call start)
__device__ int    g_off[N_NODES + 1];             // exclusive offsets
__device__ int    g_cur[N_NODES];                 // scatter cursors
__device__ unsigned long long g_desc[256];        // lookback descriptors (must be 0 at call start)
__device__ int    g_blk_counter;                  // scan block id counter (must be 0 at call start)
__device__ int2   g_edge[MAX_E];                  // {src, w_bits} sorted by dst

// ---------------------------------------------------------------------------
// K1: block-role split. Blocks [0, norm_blocks): normalize rows into g_x0
// (grid portion is exactly N_NODES*16 threads -> full warps). Remaining
// blocks: dst histogram via atomics. g_cnt arrives zeroed (static init /
// previous replay's K5 cleanup).
// ---------------------------------------------------------------------------
__global__ __launch_bounds__(256) void norm_hist_kernel(
    const float4* __restrict__ emb,
    const int*    __restrict__ adj,
    int num_edges, int norm_blocks)
{
    if ((int)blockIdx.x < norm_blocks) {
        int tid  = blockIdx.x * 256 + threadIdx.x;
        int row  = tid >> 4;
        int lane = tid & 15;
        // norm_blocks*256 == N_NODES*16 exactly; no partial warps.
        long long idx = (long long)row * DIM4 + lane;
        float4 v = emb[idx];
        float ss = v.x * v.x + v.y * v.y + v.z * v.z + v.w * v.w;
        #pragma unroll
        for (int o = 8; o; o >>= 1) ss += __shfl_xor_sync(0xffffffffu, ss, o, 16);
        float inv = 1.0f / fmaxf(sqrtf(ss), 1e-12f);
        g_x0[idx] = make_float4(v.x * inv, v.y * inv, v.z * inv, v.w * inv);
    } else {
        int e = (blockIdx.x - norm_blocks) * 256 + threadIdx.x;
        if (e < num_edges) atomicAdd(&g_cnt[adj[num_edges + e]], 1);
    }
}

// ---------------------------------------------------------------------------
// K2: single-pass exclusive scan of g_cnt -> g_off (+g_cur) via decoupled
// lookback. 196 blocks x 512 threads; block ids via atomicAdd (scheduling-
// order ids => lookback is deadlock-free; all blocks co-resident anyway).
// Descriptor word: state(high 32b: 1=aggregate, 2=inclusive) | value(low 32b).
// Single-word publish -> no separate fence needed.
// ---------------------------------------------------------------------------
__global__ __launch_bounds__(SCAN_B) void scan_lookback_kernel(int num_edges) {
    __shared__ int warp_sums[SCAN_B / 32];   // 16
    __shared__ int s_bid, s_excl, s_total;

    int t = threadIdx.x;
    if (t == 0) s_bid = atomicAdd(&g_blk_counter, 1);
    __syncthreads();
    int b   = s_bid;
    int gid = b * SCAN_B + t;
    int lane = t & 31, wid = t >> 5;

    int v = (gid < N_NODES) ? g_cnt[gid] : 0;
    int x = v;
    #pragma unroll
    for (int o = 1; o < 32; o <<= 1) {
        int y = __shfl_up_sync(0xffffffffu, x, o);
        if (lane >= o) x += y;
    }
    if (lane == 31) warp_sums[wid] = x;
    __syncthreads();
    if (wid == 0) {
        int s = (lane < SCAN_B / 32) ? warp_sums[lane] : 0;
        #pragma unroll
        for (int o = 1; o < SCAN_B / 32; o <<= 1) {
            int y = __shfl_up_sync(0xffffffffu, s, o);
            if (lane >= o) s += y;
        }
        if (lane < SCAN_B / 32) warp_sums[lane] = s;
    }
    __syncthreads();
    int prefix = (wid > 0) ? warp_sums[wid - 1] : 0;
    int incl   = prefix + x;                       // inclusive within block
    if (t == SCAN_B - 1) s_total = incl;
    __syncthreads();

    if (t == 0) {
        int total = s_total;
        if (b == 0) {
            s_excl = 0;
            atomicExch(&g_desc[0], (2ull << 32) | (unsigned)total);
        } else {
            // publish aggregate so successors can pass us while we look back
            atomicExch(&g_desc[b], (1ull << 32) | (unsigned)total);
            long long sum = 0;
            int i = b - 1;
            while (i >= 0) {
                unsigned long long w;
                do { w = *(volatile unsigned long long*)&g_desc[i]; } while ((w >> 32) == 0ull);
                sum += (unsigned)w;
                if ((w >> 32) == 2ull) break;
                i--;
            }
            s_excl = (int)sum;
            atomicExch(&g_desc[b], (2ull << 32) | (unsigned)(sum + total));
        }
        if (b == 0) g_off[N_NODES] = num_edges;
    }
    __syncthreads();

    if (gid < N_NODES) {
        int o = s_excl + (incl - v);               // global exclusive
        g_off[gid] = o;
        g_cur[gid] = o;
    }
}

// ---------------------------------------------------------------------------
// K3: scatter edges into dst-sorted order: g_edge[pos] = {src, w}
// ---------------------------------------------------------------------------
__global__ __launch_bounds__(256) void scatter_kernel(
    const int* __restrict__ adj, const float* __restrict__ wvec, int num_edges) {
    int e = blockIdx.x * blockDim.x + threadIdx.x;
    if (e >= num_edges) return;
    int dst = adj[num_edges + e];
    int pos = atomicAdd(&g_cur[dst], 1);
    g_edge[pos] = make_int2(adj[e], __float_as_int(wvec[e]));
}

// ---------------------------------------------------------------------------
// K4/K5: pull layer. One warp per node; two 16-lane halves process
// alternating in-edges; lane c owns float4 chunk c. When base0 != null
// (layer 2), also re-zeroes g_cnt/g_desc/counter for the next replay.
// (N_NODES*32 threads; divides 256 exactly -> whole warps exit together.)
// ---------------------------------------------------------------------------
__global__ __launch_bounds__(256) void pull_layer_kernel(
    const float4* __restrict__ xin,
    float4*       __restrict__ xout,
    const float4* __restrict__ base0,   // nullable
    const float4* __restrict__ base1)   // nullable
{
    int tid32 = blockIdx.x * 256 + threadIdx.x;
    if (base0) {  // layer-2 pass doubles as state cleanup for next replay
        if (tid32 < N_NODES) g_cnt[tid32] = 0;
        else if (tid32 < N_NODES + 256) {
            g_desc[tid32 - N_NODES] = 0ull;
            if (tid32 == N_NODES) g_blk_counter = 0;
        }
    }

    int node = tid32 >> 5;
    if (node >= N_NODES) return;
    int lane = threadIdx.x & 31;
    int half = lane >> 4;
    int c    = lane & 15;

    int beg = g_off[node];
    int end = g_off[node + 1];

    float4 acc = make_float4(0.f, 0.f, 0.f, 0.f);
    #pragma unroll 4
    for (int p = beg + half; p < end; p += 2) {
        int2  ew = g_edge[p];
        float w  = __int_as_float(ew.y);
        float4 v = xin[(long long)ew.x * DIM4 + c];
        acc.x += v.x * w; acc.y += v.y * w; acc.z += v.z * w; acc.w += v.w * w;
    }
    acc.x += __shfl_xor_sync(0xffffffffu, acc.x, 16);
    acc.y += __shfl_xor_sync(0xffffffffu, acc.y, 16);
    acc.z += __shfl_xor_sync(0xffffffffu, acc.z, 16);
    acc.w += __shfl_xor_sync(0xffffffffu, acc.w, 16);

    if (half == 0) {
        long long idx = (long long)node * DIM4 + c;
        if (base0) {
            float4 b0 = base0[idx], b1 = base1[idx];
            acc.x += b0.x + b1.x; acc.y += b0.y + b1.y;
            acc.z += b0.z + b1.z; acc.w += b0.w + b1.w;
        }
        xout[idx] = acc;
    }
}

// ---------------------------------------------------------------------------
// kernel_launch
// ---------------------------------------------------------------------------
extern "C" void kernel_launch(void* const* d_in, const int* in_sizes, int n_in,
                              void* d_out, int out_size) {
    const float4* emb = (const float4*)d_in[0]; // [100000, 64] f32
    const float*  wv  = (const float*)d_in[1];  // [E] f32
    const int*    adj = (const int*)d_in[2];    // [2, E] int32

    int E = in_sizes[1];

    float4* x0; float4* x1;
    cudaGetSymbolAddress((void**)&x0, g_x0);
    cudaGetSymbolAddress((void**)&x1, g_x1);
    float4* out4 = reinterpret_cast<float4*>(d_out);

    const int T = 256;
    int norm_blocks = (N_NODES * 16) / T;           // 6250, exact
    int hist_blocks = (E + T - 1) / T;

    // K1: normalize + histogram (independent; role split by block)
    norm_hist_kernel<<<norm_blocks + hist_blocks, T>>>(emb, adj, E, norm_blocks);
    // K2: single-pass scan -> g_off, g_cur
    scan_lookback_kernel<<<NUM_SB, SCAN_B>>>(E);
    // K3: scatter into dst-sorted edge array
    scatter_kernel<<<(E + T - 1) / T, T>>>(adj, wv, E);
    // K4: layer 1: x1 = A x0
    pull_layer_kernel<<<(N_NODES * 32) / T, T>>>(x0, x1, nullptr, nullptr);
    // K5: layer 2 fused: out = x0 + x1 + A x1 (+ state cleanup)
    pull_layer_kernel<<<(N_NODES * 32) / T, T>>>(x1, out4, x0, x1);
}

// round 14
// speedup vs baseline: 1.0161x; 1.0161x over previous
#include <cuda_runtime.h>
#include <stdint.h>

// EGCN pull-mode, consolidated pipeline (5 launches):
//   K1 norm+hist (block-role split)
//   K2 single-pass decoupled-lookback scan -> g_off, g_cur
//   K3 scatter edges into dst-sorted records (+ replay-state cleanup)
//   K4 pull layer 1: x1 = A x0
//   K5 pull layer 2 (fused): out = x0 + x1 + A x1
// N=100000, DIM=64, E=1.6M. adj arrives int32.

constexpr int N_NODES = 100000;
constexpr int DIM     = 64;
constexpr int DIM4    = DIM / 4;     // 16 float4 per row
constexpr int MAX_E   = 1600000;
constexpr int SCAN_B  = 512;
constexpr int NUM_SB  = (N_NODES + SCAN_B - 1) / SCAN_B;      // 196

// ---- device scratch (allocation-free; zero-initialized at module load) ----
__device__ float4 g_x0[(long long)N_NODES * DIM4];
__device__ float4 g_x1[(long long)N_NODES * DIM4];
__device__ int    g_cnt[N_NODES];                 // in-degree histogram (0 at call start)
__device__ int    g_off[N_NODES + 1];             // exclusive offsets
__device__ int    g_cur[N_NODES];                 // scatter cursors
__device__ unsigned long long g_desc[256];        // lookback descriptors (0 at call start)
__device__ int    g_blk_counter;                  // scan block id counter (0 at call start)
__device__ int2   g_edge[MAX_E];                  // {src, w_bits} sorted by dst

// ---------------------------------------------------------------------------
// K1: block-role split. Blocks [0, norm_blocks): normalize rows into g_x0
// (exactly N_NODES*16 threads -> full warps). Remaining blocks: dst histogram.
// ---------------------------------------------------------------------------
__global__ __launch_bounds__(256) void norm_hist_kernel(
    const float4* __restrict__ emb,
    const int*    __restrict__ adj,
    int num_edges, int norm_blocks)
{
    if ((int)blockIdx.x < norm_blocks) {
        int tid  = blockIdx.x * 256 + threadIdx.x;
        int row  = tid >> 4;
        int lane = tid & 15;
        long long idx = (long long)row * DIM4 + lane;
        float4 v = emb[idx];
        float ss = v.x * v.x + v.y * v.y + v.z * v.z + v.w * v.w;
        #pragma unroll
        for (int o = 8; o; o >>= 1) ss += __shfl_xor_sync(0xffffffffu, ss, o, 16);
        float inv = 1.0f / fmaxf(sqrtf(ss), 1e-12f);
        g_x0[idx] = make_float4(v.x * inv, v.y * inv, v.z * inv, v.w * inv);
    } else {
        int e = (blockIdx.x - norm_blocks) * 256 + threadIdx.x;
        if (e < num_edges) atomicAdd(&g_cnt[adj[num_edges + e]], 1);
    }
}

// ---------------------------------------------------------------------------
// K2: single-pass exclusive scan of g_cnt -> g_off (+g_cur), decoupled
// lookback. Block ids via atomicAdd => scheduling-order, deadlock-free.
// Descriptor: state(hi32: 1=aggregate, 2=inclusive) | value(lo32).
// ---------------------------------------------------------------------------
__global__ __launch_bounds__(SCAN_B) void scan_lookback_kernel(int num_edges) {
    __shared__ int warp_sums[SCAN_B / 32];   // 16
    __shared__ int s_bid, s_excl, s_total;

    int t = threadIdx.x;
    if (t == 0) s_bid = atomicAdd(&g_blk_counter, 1);
    __syncthreads();
    int b   = s_bid;
    int gid = b * SCAN_B + t;
    int lane = t & 31, wid = t >> 5;

    int v = (gid < N_NODES) ? g_cnt[gid] : 0;
    int x = v;
    #pragma unroll
    for (int o = 1; o < 32; o <<= 1) {
        int y = __shfl_up_sync(0xffffffffu, x, o);
        if (lane >= o) x += y;
    }
    if (lane == 31) warp_sums[wid] = x;
    __syncthreads();
    if (wid == 0) {
        int s = (lane < SCAN_B / 32) ? warp_sums[lane] : 0;
        #pragma unroll
        for (int o = 1; o < SCAN_B / 32; o <<= 1) {
            int y = __shfl_up_sync(0xffffffffu, s, o);
            if (lane >= o) s += y;
        }
        if (lane < SCAN_B / 32) warp_sums[lane] = s;
    }
    __syncthreads();
    int prefix = (wid > 0) ? warp_sums[wid - 1] : 0;
    int incl   = prefix + x;
    if (t == SCAN_B - 1) s_total = incl;
    __syncthreads();

    if (t == 0) {
        int total = s_total;
        if (b == 0) {
            s_excl = 0;
            atomicExch(&g_desc[0], (2ull << 32) | (unsigned)total);
        } else {
            atomicExch(&g_desc[b], (1ull << 32) | (unsigned)total);
            long long sum = 0;
            int i = b - 1;
            while (i >= 0) {
                unsigned long long w;
                do { w = *(volatile unsigned long long*)&g_desc[i]; } while ((w >> 32) == 0ull);
                sum += (unsigned)w;
                if ((w >> 32) == 2ull) break;
                i--;
            }
            s_excl = (int)sum;
            atomicExch(&g_desc[b], (2ull << 32) | (unsigned)(sum + total));
        }
        if (b == 0) g_off[N_NODES] = num_edges;
    }
    __syncthreads();

    if (gid < N_NODES) {
        int o = s_excl + (incl - v);
        g_off[gid] = o;
        g_cur[gid] = o;
    }
}

// ---------------------------------------------------------------------------
// K3: scatter edges into dst-sorted order; ALSO re-zeroes replay state
// (legal here: scan, the last reader of g_cnt/g_desc/counter, has completed).
// ---------------------------------------------------------------------------
__global__ __launch_bounds__(256) void scatter_kernel(
    const int* __restrict__ adj, const float* __restrict__ wvec, int num_edges) {
    int e = blockIdx.x * blockDim.x + threadIdx.x;
    if (e < N_NODES) g_cnt[e] = 0;
    else if (e < N_NODES + 256) {
        g_desc[e - N_NODES] = 0ull;
        if (e == N_NODES) g_blk_counter = 0;
    }
    if (e >= num_edges) return;
    int dst = adj[num_edges + e];
    int pos = atomicAdd(&g_cur[dst], 1);
    g_edge[pos] = make_int2(adj[e], __float_as_int(wvec[e]));
}

// ---------------------------------------------------------------------------
// K4/K5: pull layer. One warp per node; two 16-lane halves process
// alternating in-edges; lane c owns float4 chunk c. Edge-record loads are
// software-pipelined: the next record is in flight during the current
// gather, breaking the record->gather dependent chain across iterations.
// (N_NODES*32 threads; divides 256 exactly -> whole warps exit together.)
// ---------------------------------------------------------------------------
__global__ __launch_bounds__(256) void pull_layer_kernel(
    const float4* __restrict__ xin,
    float4*       __restrict__ xout,
    const float4* __restrict__ base0,   // nullable
    const float4* __restrict__ base1)   // nullable
{
    int node = (blockIdx.x * 256 + threadIdx.x) >> 5;
    if (node >= N_NODES) return;
    int lane = threadIdx.x & 31;
    int half = lane >> 4;
    int c    = lane & 15;

    int beg = g_off[node];
    int end = g_off[node + 1];

    float4 acc = make_float4(0.f, 0.f, 0.f, 0.f);
    int p = beg + half;
    if (p < end) {
        int2 ew = g_edge[p];                     // prologue record
        p += 2;
        #pragma unroll 4
        for (; p < end; p += 2) {
            int2 nx = g_edge[p];                 // prefetch next record
            float w  = __int_as_float(ew.y);
            float4 v = xin[(long long)ew.x * DIM4 + c];
            acc.x += v.x * w; acc.y += v.y * w;
            acc.z += v.z * w; acc.w += v.w * w;
            ew = nx;
        }
        // epilogue: last record
        float w  = __int_as_float(ew.y);
        float4 v = xin[(long long)ew.x * DIM4 + c];
        acc.x += v.x * w; acc.y += v.y * w;
        acc.z += v.z * w; acc.w += v.w * w;
    }

    acc.x += __shfl_xor_sync(0xffffffffu, acc.x, 16);
    acc.y += __shfl_xor_sync(0xffffffffu, acc.y, 16);
    acc.z += __shfl_xor_sync(0xffffffffu, acc.z, 16);
    acc.w += __shfl_xor_sync(0xffffffffu, acc.w, 16);

    if (half == 0) {
        long long idx = (long long)node * DIM4 + c;
        if (base0) {
            float4 b0 = base0[idx], b1 = base1[idx];
            acc.x += b0.x + b1.x; acc.y += b0.y + b1.y;
            acc.z += b0.z + b1.z; acc.w += b0.w + b1.w;
        }
        xout[idx] = acc;
    }
}

// ---------------------------------------------------------------------------
// kernel_launch
// ---------------------------------------------------------------------------
extern "C" void kernel_launch(void* const* d_in, const int* in_sizes, int n_in,
                              void* d_out, int out_size) {
    const float4* emb = (const float4*)d_in[0]; // [100000, 64] f32
    const float*  wv  = (const float*)d_in[1];  // [E] f32
    const int*    adj = (const int*)d_in[2];    // [2, E] int32

    int E = in_sizes[1];

    float4* x0; float4* x1;
    cudaGetSymbolAddress((void**)&x0, g_x0);
    cudaGetSymbolAddress((void**)&x1, g_x1);
    float4* out4 = reinterpret_cast<float4*>(d_out);

    const int T = 256;
    int norm_blocks = (N_NODES * 16) / T;           // 6250, exact
    int hist_blocks = (E + T - 1) / T;

    // K1: normalize + histogram (independent; role split by block)
    norm_hist_kernel<<<norm_blocks + hist_blocks, T>>>(emb, adj, E, norm_blocks);
    // K2: single-pass scan -> g_off, g_cur
    scan_lookback_kernel<<<NUM_SB, SCAN_B>>>(E);
    // K3: scatter into dst-sorted edge array (+ state cleanup)
    scatter_kernel<<<(E + T - 1) / T, T>>>(adj, wv, E);
    // K4: layer 1: x1 = A x0
    pull_layer_kernel<<<(N_NODES * 32) / T, T>>>(x0, x1, nullptr, nullptr);
    // K5: layer 2 fused: out = x0 + x1 + A x1
    pull_layer_kernel<<<(N_NODES * 32) / T, T>>>(x1, out4, x0, x1);
}

// round 15
// speedup vs baseline: 1.0330x; 1.0166x over previous
#include <cuda_runtime.h>
#include <cuda_fp16.h>
#include <stdint.h>

// EGCN pull-mode with fp16 gather storage (accumulate fp32):
//   K1 norm+hist   K2 lookback scan   K3 scatter(+cleanup)
//   K4 pull1: x1=A x0 (gather fp16 x0h; write x1 fp32 + x1h fp16)
//   K5 pull2: out = x0 + x1 + A x1 (gather fp16 x1h; base fp32)
// N=100000, DIM=64, E=1.6M. adj arrives int32.

constexpr int N_NODES = 100000;
constexpr int DIM     = 64;
constexpr int DIM4    = DIM / 4;     // 16 float4 / 16 uint2 per row
constexpr int MAX_E   = 1600000;
constexpr int SCAN_B  = 512;
constexpr int NUM_SB  = (N_NODES + SCAN_B - 1) / SCAN_B;      // 196

// ---- device scratch (allocation-free; zero-initialized at module load) ----
__device__ float4 g_x0[N_NODES * DIM4];    // fp32 x0 (base term)
__device__ float4 g_x1[N_NODES * DIM4];    // fp32 x1 (base term)
__device__ uint2  g_h0[N_NODES * DIM4];    // fp16 x0 (gather copy; row=128B=1 line)
__device__ uint2  g_h1[N_NODES * DIM4];    // fp16 x1 (gather copy)
__device__ int    g_cnt[N_NODES];
__device__ int    g_off[N_NODES + 1];
__device__ int    g_cur[N_NODES];
__device__ unsigned long long g_desc[256];
__device__ int    g_blk_counter;
__device__ int2   g_edge[MAX_E];           // {src, w_bits} sorted by dst

__device__ __forceinline__ uint2 pack_half4(float4 r) {
    __half2 a = __floats2half2_rn(r.x, r.y);
    __half2 b = __floats2half2_rn(r.z, r.w);
    uint2 u;
    u.x = *reinterpret_cast<unsigned*>(&a);
    u.y = *reinterpret_cast<unsigned*>(&b);
    return u;
}

// ---------------------------------------------------------------------------
// K1: block-role split. Blocks [0, norm_blocks): normalize rows into g_x0 and
// g_h0 (exactly N_NODES*16 threads -> full warps). Remaining: dst histogram.
// ---------------------------------------------------------------------------
__global__ __launch_bounds__(256) void norm_hist_kernel(
    const float4* __restrict__ emb,
    const int*    __restrict__ adj,
    int num_edges, int norm_blocks)
{
    if ((int)blockIdx.x < norm_blocks) {
        int tid  = blockIdx.x * 256 + threadIdx.x;
        int row  = tid >> 4;
        int lane = tid & 15;
        int idx = row * DIM4 + lane;               // < 1.6M, fits int
        float4 v = emb[idx];
        float ss = v.x * v.x + v.y * v.y + v.z * v.z + v.w * v.w;
        #pragma unroll
        for (int o = 8; o; o >>= 1) ss += __shfl_xor_sync(0xffffffffu, ss, o, 16);
        float inv = 1.0f / fmaxf(sqrtf(ss), 1e-12f);
        float4 r = make_float4(v.x * inv, v.y * inv, v.z * inv, v.w * inv);
        g_x0[idx] = r;
        g_h0[idx] = pack_half4(r);
    } else {
        int e = (blockIdx.x - norm_blocks) * 256 + threadIdx.x;
        if (e < num_edges) atomicAdd(&g_cnt[adj[num_edges + e]], 1);
    }
}

// ---------------------------------------------------------------------------
// K2: single-pass exclusive scan of g_cnt -> g_off (+g_cur), decoupled
// lookback. Block ids via atomicAdd => scheduling-order, deadlock-free.
// ---------------------------------------------------------------------------
__global__ __launch_bounds__(SCAN_B) void scan_lookback_kernel(int num_edges) {
    __shared__ int warp_sums[SCAN_B / 32];
    __shared__ int s_bid, s_excl, s_total;

    int t = threadIdx.x;
    if (t == 0) s_bid = atomicAdd(&g_blk_counter, 1);
    __syncthreads();
    int b   = s_bid;
    int gid = b * SCAN_B + t;
    int lane = t & 31, wid = t >> 5;

    int v = (gid < N_NODES) ? g_cnt[gid] : 0;
    int x = v;
    #pragma unroll
    for (int o = 1; o < 32; o <<= 1) {
        int y = __shfl_up_sync(0xffffffffu, x, o);
        if (lane >= o) x += y;
    }
    if (lane == 31) warp_sums[wid] = x;
    __syncthreads();
    if (wid == 0) {
        int s = (lane < SCAN_B / 32) ? warp_sums[lane] : 0;
        #pragma unroll
        for (int o = 1; o < SCAN_B / 32; o <<= 1) {
            int y = __shfl_up_sync(0xffffffffu, s, o);
            if (lane >= o) s += y;
        }
        if (lane < SCAN_B / 32) warp_sums[lane] = s;
    }
    __syncthreads();
    int prefix = (wid > 0) ? warp_sums[wid - 1] : 0;
    int incl   = prefix + x;
    if (t == SCAN_B - 1) s_total = incl;
    __syncthreads();

    if (t == 0) {
        int total = s_total;
        if (b == 0) {
            s_excl = 0;
            atomicExch(&g_desc[0], (2ull << 32) | (unsigned)total);
        } else {
            atomicExch(&g_desc[b], (1ull << 32) | (unsigned)total);
            long long sum = 0;
            int i = b - 1;
            while (i >= 0) {
                unsigned long long w;
                do { w = *(volatile unsigned long long*)&g_desc[i]; } while ((w >> 32) == 0ull);
                sum += (unsigned)w;
                if ((w >> 32) == 2ull) break;
                i--;
            }
            s_excl = (int)sum;
            atomicExch(&g_desc[b], (2ull << 32) | (unsigned)(sum + total));
        }
        if (b == 0) g_off[N_NODES] = num_edges;
    }
    __syncthreads();

    if (gid < N_NODES) {
        int o = s_excl + (incl - v);
        g_off[gid] = o;
        g_cur[gid] = o;
    }
}

// ---------------------------------------------------------------------------
// K3: scatter edges into dst-sorted order; re-zeroes replay state (legal:
// scan, the last reader of g_cnt/g_desc/counter, has completed).
// ---------------------------------------------------------------------------
__global__ __launch_bounds__(256) void scatter_kernel(
    const int* __restrict__ adj, const float* __restrict__ wvec, int num_edges) {
    int e = blockIdx.x * blockDim.x + threadIdx.x;
    if (e < N_NODES) g_cnt[e] = 0;
    else if (e < N_NODES + 256) {
        g_desc[e - N_NODES] = 0ull;
        if (e == N_NODES) g_blk_counter = 0;
    }
    if (e >= num_edges) return;
    int dst = adj[num_edges + e];
    int pos = atomicAdd(&g_cur[dst], 1);
    g_edge[pos] = make_int2(adj[e], __float_as_int(wvec[e]));
}

// ---------------------------------------------------------------------------
// K4/K5: pull layer, fp16 gathers. One warp per node; two 16-lane halves
// process alternating in-edges. Lane c owns elements [4c,4c+4): loads uint2
// (4 halves, 8B; 16 lanes = 128B = one line per edge), converts, fp32 FFMA.
// Layer 1 (base0==null): writes x1 fp32 + x1h fp16.
// Layer 2 (base0!=null): out = base0 + base1 + A xin.
// (N_NODES*32 threads; divides 256 exactly -> whole warps exit together.)
// ---------------------------------------------------------------------------
__global__ __launch_bounds__(256) void pull_layer_kernel(
    const uint2*  __restrict__ hin,     // fp16 gather source
    float4*       __restrict__ xout,    // fp32 output (x1 or out)
    uint2*        __restrict__ hout,    // fp16 copy of output (layer 1 only)
    const float4* __restrict__ base0,   // nullable (layer 2)
    const float4* __restrict__ base1)   // nullable (layer 2)
{
    int node = (blockIdx.x * 256 + threadIdx.x) >> 5;
    if (node >= N_NODES) return;
    int lane = threadIdx.x & 31;
    int half = lane >> 4;
    int c    = lane & 15;

    int beg = g_off[node];
    int end = g_off[node + 1];

    float4 acc = make_float4(0.f, 0.f, 0.f, 0.f);
    #pragma unroll 4
    for (int p = beg + half; p < end; p += 2) {
        int2  ew = g_edge[p];
        float w  = __int_as_float(ew.y);
        uint2 u  = hin[ew.x * DIM4 + c];
        __half2 h01 = *reinterpret_cast<__half2*>(&u.x);
        __half2 h23 = *reinterpret_cast<__half2*>(&u.y);
        float2 f01 = __half22float2(h01);
        float2 f23 = __half22float2(h23);
        acc.x += f01.x * w; acc.y += f01.y * w;
        acc.z += f23.x * w; acc.w += f23.y * w;
    }
    acc.x += __shfl_xor_sync(0xffffffffu, acc.x, 16);
    acc.y += __shfl_xor_sync(0xffffffffu, acc.y, 16);
    acc.z += __shfl_xor_sync(0xffffffffu, acc.z, 16);
    acc.w += __shfl_xor_sync(0xffffffffu, acc.w, 16);

    if (half == 0) {
        int idx = node * DIM4 + c;
        if (base0) {
            float4 b0 = base0[idx], b1 = base1[idx];
            acc.x += b0.x + b1.x; acc.y += b0.y + b1.y;
            acc.z += b0.z + b1.z; acc.w += b0.w + b1.w;
        }
        xout[idx] = acc;
        if (hout) hout[idx] = pack_half4(acc);
    }
}

// ---------------------------------------------------------------------------
// kernel_launch
// ---------------------------------------------------------------------------
extern "C" void kernel_launch(void* const* d_in, const int* in_sizes, int n_in,
                              void* d_out, int out_size) {
    const float4* emb = (const float4*)d_in[0]; // [100000, 64] f32
    const float*  wv  = (const float*)d_in[1];  // [E] f32
    const int*    adj = (const int*)d_in[2];    // [2, E] int32

    int E = in_sizes[1];

    float4* x0; float4* x1; uint2* h0; uint2* h1;
    cudaGetSymbolAddress((void**)&x0, g_x0);
    cudaGetSymbolAddress((void**)&x1, g_x1);
    cudaGetSymbolAddress((void**)&h0, g_h0);
    cudaGetSymbolAddress((void**)&h1, g_h1);
    float4* out4 = reinterpret_cast<float4*>(d_out);

    const int T = 256;
    int norm_blocks = (N_NODES * 16) / T;           // 6250, exact
    int hist_blocks = (E + T - 1) / T;

    // K1: normalize (fp32 + fp16 copies) + histogram
    norm_hist_kernel<<<norm_blocks + hist_blocks, T>>>(emb, adj, E, norm_blocks);
    // K2: single-pass scan -> g_off, g_cur
    scan_lookback_kernel<<<NUM_SB, SCAN_B>>>(E);
    // K3: scatter into dst-sorted edge array (+ state cleanup)
    scatter_kernel<<<(E + T - 1) / T, T>>>(adj, wv, E);
    // K4: layer 1: x1 = A x0 (gather h0; write x1 fp32 + h1 fp16)
    pull_layer_kernel<<<(N_NODES * 32) / T, T>>>(h0, x1, h1, nullptr, nullptr);
    // K5: layer 2: out = x0 + x1 + A x1 (gather h1)
    pull_layer_kernel<<<(N_NODES * 32) / T, T>>>(h1, out4, nullptr, x0, x1);
}